// round 3
// baseline (speedup 1.0000x reference)
#include <cuda_runtime.h>

#define H     128
#define DD    2
#define TOBS  20
#define PREDN 30
#define BATCH 16384
#define RR    16          // batch rows per block
#define PP    8           // row pairs (RR/2)
#define NTHR  128
#define KT    4
#define NT    (H/KT)      // 32

typedef unsigned long long ull;

// __device__ scratch (allocation-free rule)
__device__ float g_wt[4][H][4*H];       // [w][k][4*j+g], w: 0=pe,1=se,2=sd,3=pd
__device__ float g_b [4][4*H];          // combined bih+bhh, interleaved [4*j+g]
__device__ float g_wi[4][4*H][DD];      // Wih interleaved
__device__ float g_hln[2][BATCH][H];    // layernormed encoder h (0=pos,1=speed)
__device__ float g_cln[2][BATCH][H];    // layernormed encoder c

// ---------- helpers ----------
__device__ __forceinline__ ull pk(float a, float b){
    ull r; asm("mov.b64 %0, {%1, %2};" : "=l"(r) : "f"(a), "f"(b)); return r;
}
__device__ __forceinline__ float2 up(ull v){
    float2 r; asm("mov.b64 {%0, %1}, %2;" : "=f"(r.x), "=f"(r.y) : "l"(v)); return r;
}
__device__ __forceinline__ void fma2(ull& d, ull a, ull b){
    asm("fma.rn.f32x2 %0, %1, %2, %0;" : "+l"(d) : "l"(a), "l"(b));
}
__device__ __forceinline__ float sigm(float x){ return 1.0f/(1.0f + __expf(-x)); }
__device__ __forceinline__ float tanh_(float x){
    float a = fabsf(x);
    float t = 1.0f - 2.0f/(__expf(2.0f*a) + 1.0f);
    return copysignf(t, x);
}

// one K-tile of the 512x128 gate GEMM: 4 k's, 32 FFMA2 per k
#define GTILE(WB, KB) \
    _Pragma("unroll") \
    for (int i_ = 0; i_ < KT; i_++){ \
        const ulonglong2* hp2_ = (const ulonglong2*)(hb + ((KB)+i_)*RR); \
        ulonglong2 q0_=hp2_[0], q1_=hp2_[1], q2_=hp2_[2], q3_=hp2_[3]; \
        ull hp_[PP] = {q0_.x,q0_.y,q1_.x,q1_.y,q2_.x,q2_.y,q3_.x,q3_.y}; \
        float4 wv_ = WB[i_]; \
        ull wg_[4] = {pk(wv_.x,wv_.x), pk(wv_.y,wv_.y), pk(wv_.z,wv_.z), pk(wv_.w,wv_.w)}; \
        _Pragma("unroll") \
        for (int g_ = 0; g_ < 4; g_++){ \
            _Pragma("unroll") \
            for (int p_ = 0; p_ < PP; p_++) fma2(acc[g_][p_], wg_[g_], hp_[p_]); \
        } \
    }

// gates(acc) += Whh @ h  for this thread's unit j. wtj points at unit j's float4 column.
__device__ __forceinline__ void gemm_hh(const float4* __restrict__ wtj,
                                        const float* __restrict__ hb,
                                        ull (&acc)[4][PP]){
    float4 wb0[KT], wb1[KT];
    #pragma unroll
    for (int i = 0; i < KT; i++) wb0[i] = __ldg(wtj + i*H);
    #pragma unroll 1
    for (int kt = 0; kt < NT; kt += 2){
        #pragma unroll
        for (int i = 0; i < KT; i++) wb1[i] = __ldg(wtj + ((kt+1)*KT + i)*H);
        GTILE(wb0, kt*KT)
        if (kt + 2 < NT){
            #pragma unroll
            for (int i = 0; i < KT; i++) wb0[i] = __ldg(wtj + ((kt+2)*KT + i)*H);
        }
        GTILE(wb1, (kt+1)*KT)
    }
}

// acc init: bias + Wih @ x  (x per row from two float2's)
#define ACC_INIT(XA, XB) \
    _Pragma("unroll") \
    for (int g_ = 0; g_ < 4; g_++){ \
        float a0_ = fmaf(wi1[g_], (XA).y, fmaf(wi0[g_], (XA).x, bb[g_])); \
        float a1_ = fmaf(wi1[g_], (XB).y, fmaf(wi0[g_], (XB).x, bb[g_])); \
        acc[g_][p] = pk(a0_, a1_); \
    }

// LSTM activation epilogue: updates cst, produces packed hnew
#define LSTM_ACT() \
    _Pragma("unroll") \
    for (int p_ = 0; p_ < PP; p_++){ \
        float2 iv = up(acc[0][p_]), fv = up(acc[1][p_]); \
        float2 gv = up(acc[2][p_]), ov = up(acc[3][p_]); \
        float2 cv = up(cst[p_]); \
        float c0 = sigm(fv.x)*cv.x + sigm(iv.x)*tanh_(gv.x); \
        float c1 = sigm(fv.y)*cv.y + sigm(iv.y)*tanh_(gv.y); \
        cst[p_] = pk(c0, c1); \
        hnew[p_] = pk(sigm(ov.x)*tanh_(c0), sigm(ov.y)*tanh_(c1)); \
    }

// ---------- prep kernels ----------
__global__ void prep_w(const float* w0, const float* w1, const float* w2, const float* w3){
    const float* W[4] = {w0, w1, w2, w3};
    int idx = blockIdx.x*blockDim.x + threadIdx.x;   // < 4*65536
    int w   = idx >> 16;
    int rem = idx & 65535;
    int k  = rem >> 9;          // 0..127
    int jg = rem & 511;
    int j  = jg >> 2, g = jg & 3;
    g_wt[w][k][jg] = W[w][(g*H + j)*H + k];
}

__global__ void prep_b(const float* wiA, const float* wiB, const float* wiC, const float* wiD,
                       const float* biA, const float* bhA, const float* biB, const float* bhB,
                       const float* biC, const float* bhC, const float* biD, const float* bhD){
    const float* WI[4] = {wiA, wiB, wiC, wiD};
    const float* BI[4] = {biA, biB, biC, biD};
    const float* BH[4] = {bhA, bhB, bhC, bhD};
    int w = blockIdx.x, jg = threadIdx.x;
    int j = jg >> 2, g = jg & 3;
    int row = g*H + j;
    g_b [w][jg]    = BI[w][row] + BH[w][row];
    g_wi[w][jg][0] = WI[w][row*DD + 0];
    g_wi[w][jg][1] = WI[w][row*DD + 1];
}

// ---------- encoder: 20 LSTM steps + fused LayerNorm ----------
__global__ void __launch_bounds__(NTHR)
encoder_kernel(const float* __restrict__ pos, const float* __restrict__ speed,
               const float* __restrict__ ln_g, const float* __restrict__ ln_b){
    int w    = blockIdx.y;               // 0 = pos(pe), 1 = speed(se)
    int base = blockIdx.x * RR;
    int j    = threadIdx.x;
    const float* x = (w == 0) ? pos : speed;

    __shared__ __align__(16) float hbuf[2][H][RR];
    __shared__ float m_s[RR], rs_s[RR];

    float wi0[4], wi1[4], bb[4];
    #pragma unroll
    for (int g = 0; g < 4; g++){
        wi0[g] = g_wi[w][4*j+g][0];
        wi1[g] = g_wi[w][4*j+g][1];
        bb[g]  = g_b [w][4*j+g];
    }
    const float4* wtj = ((const float4*)g_wt[w]) + j;

    ull cst[PP];
    #pragma unroll
    for (int p = 0; p < PP; p++) cst[p] = 0ull;
    #pragma unroll
    for (int p = 0; p < PP; p++) ((ull*)&hbuf[0][j][0])[p] = 0ull;
    __syncthreads();

    for (int t = 0; t < TOBS; t++){
        const float* hb = &hbuf[t & 1][0][0];
        float*       hw = &hbuf[(t + 1) & 1][0][0];
        ull acc[4][PP];
        const float2* xrow = (const float2*)(x + (size_t)t*BATCH*DD + (size_t)base*DD);
        #pragma unroll
        for (int p = 0; p < PP; p++){
            float2 xa = __ldg(&xrow[2*p]), xb = __ldg(&xrow[2*p+1]);
            ACC_INIT(xa, xb)
        }
        gemm_hh(wtj, hb, acc);
        ull hnew[PP];
        LSTM_ACT()
        #pragma unroll
        for (int p = 0; p < PP; p++) ((ull*)&hw[j*RR])[p] = hnew[p];
        __syncthreads();
    }

    // LayerNorm h (final h is in hbuf[TOBS & 1] == hbuf[0])
    float* hf = &hbuf[TOBS & 1][0][0];
    if (j < RR){
        float s1 = 0.f, s2 = 0.f;
        for (int k = 0; k < H; k++){ float v = hf[k*RR + j]; s1 += v; s2 += v*v; }
        float m  = s1 * (1.0f/H);
        float vr = s2 * (1.0f/H) - m*m;
        m_s[j] = m; rs_s[j] = rsqrtf(vr + 1e-5f);
    }
    __syncthreads();
    float lg = ln_g[j], lb = ln_b[j];
    #pragma unroll
    for (int r = 0; r < RR; r++){
        float v = hf[j*RR + r];
        g_hln[w][base + r][j] = (v - m_s[r]) * rs_s[r] * lg + lb;
    }
    // LayerNorm c (stage through the other buffer)
    float* cf = &hbuf[(TOBS & 1) ^ 1][0][0];
    #pragma unroll
    for (int p = 0; p < PP; p++) ((ull*)&cf[j*RR])[p] = cst[p];
    __syncthreads();
    if (j < RR){
        float s1 = 0.f, s2 = 0.f;
        for (int k = 0; k < H; k++){ float v = cf[k*RR + j]; s1 += v; s2 += v*v; }
        float m  = s1 * (1.0f/H);
        float vr = s2 * (1.0f/H) - m*m;
        m_s[j] = m; rs_s[j] = rsqrtf(vr + 1e-5f);
    }
    __syncthreads();
    #pragma unroll
    for (int r = 0; r < RR; r++){
        float v = cf[j*RR + r];
        g_cln[w][base + r][j] = (v - m_s[r]) * rs_s[r] * lg + lb;
    }
}

// ---------- decoder: 30 LSTM steps + FC feedback + output stores ----------
__global__ void __launch_bounds__(NTHR)
decoder_kernel(const float* __restrict__ pos, const float* __restrict__ speed,
               const float* __restrict__ wfc, const float* __restrict__ bfc,
               float* __restrict__ out){
    int chain = blockIdx.y;              // 0: speed chain (sd), 1: pos chain (pd)
    int w     = 2 + chain;
    int base  = blockIdx.x * RR;
    int j     = threadIdx.x;

    __shared__ __align__(16) float hbuf[2][H][RR];
    __shared__ float x_s[RR][2];
    __shared__ float wfc_s[2][H];

    float wi0[4], wi1[4], bb[4];
    #pragma unroll
    for (int g = 0; g < 4; g++){
        wi0[g] = g_wi[w][4*j+g][0];
        wi1[g] = g_wi[w][4*j+g][1];
        bb[g]  = g_b [w][4*j+g];
    }
    const float4* wtj = ((const float4*)g_wt[w]) + j;

    // initial states
    ull cst[PP];
    if (chain == 0){
        #pragma unroll
        for (int r = 0; r < RR; r++)
            hbuf[0][j][r] = g_hln[0][base + r][j] + g_hln[1][base + r][j];
        #pragma unroll
        for (int p = 0; p < PP; p++){
            float c0 = g_cln[0][base + 2*p    ][j] + g_cln[1][base + 2*p    ][j];
            float c1 = g_cln[0][base + 2*p + 1][j] + g_cln[1][base + 2*p + 1][j];
            cst[p] = pk(c0, c1);
        }
    } else {
        #pragma unroll
        for (int r = 0; r < RR; r++)
            hbuf[0][j][r] = g_hln[0][base + r][j];
        #pragma unroll
        for (int p = 0; p < PP; p++)
            cst[p] = pk(g_cln[0][base + 2*p][j], g_cln[0][base + 2*p + 1][j]);
    }
    wfc_s[0][j] = wfc[j];
    wfc_s[1][j] = wfc[H + j];
    float bf0 = bfc[0], bf1 = bfc[1];
    if (j < RR){
        const float* xs = ((chain == 0) ? speed : pos)
                        + (size_t)(TOBS - 1)*BATCH*DD + (size_t)(base + j)*DD;
        x_s[j][0] = xs[0]; x_s[j][1] = xs[1];
    }
    float* outb = out + ((chain == 0) ? (size_t)PREDN*BATCH*DD : (size_t)0);
    __syncthreads();

    for (int t = 0; t < PREDN; t++){
        const float* hb = &hbuf[t & 1][0][0];
        float*       hw = &hbuf[(t + 1) & 1][0][0];
        ull acc[4][PP];
        #pragma unroll
        for (int p = 0; p < PP; p++){
            float2 xa = make_float2(x_s[2*p  ][0], x_s[2*p  ][1]);
            float2 xb = make_float2(x_s[2*p+1][0], x_s[2*p+1][1]);
            ACC_INIT(xa, xb)
        }
        gemm_hh(wtj, hb, acc);
        ull hnew[PP];
        LSTM_ACT()
        #pragma unroll
        for (int p = 0; p < PP; p++) ((ull*)&hw[j*RR])[p] = hnew[p];
        __syncthreads();

        // FC feedback: x_next = h @ Wfc.T + bfc ; also store output
        if (j < 64){
            int r = j >> 2, q = j & 3;
            float s0 = 0.f, s1 = 0.f;
            #pragma unroll
            for (int i = 0; i < 32; i++){
                int jj = q + 4*i;
                float hv = hw[jj*RR + r];
                s0 = fmaf(hv, wfc_s[0][jj], s0);
                s1 = fmaf(hv, wfc_s[1][jj], s1);
            }
            s0 += __shfl_xor_sync(0xffffffffu, s0, 1);
            s0 += __shfl_xor_sync(0xffffffffu, s0, 2);
            s1 += __shfl_xor_sync(0xffffffffu, s1, 1);
            s1 += __shfl_xor_sync(0xffffffffu, s1, 2);
            if (q == 0){
                float o0 = s0 + bf0, o1 = s1 + bf1;
                x_s[r][0] = o0; x_s[r][1] = o1;
                float* op = outb + ((size_t)t*BATCH + base + r)*DD;
                ((float2*)op)[0] = make_float2(o0, o1);
            }
        }
        __syncthreads();
    }
}

// ---------- launch ----------
extern "C" void kernel_launch(void* const* d_in, const int* in_sizes, int n_in,
                              void* d_out, int out_size){
    (void)in_sizes; (void)n_in; (void)out_size;
    const float* pos   = (const float*)d_in[0];
    const float* speed = (const float*)d_in[1];

    prep_w<<<1024, 256>>>((const float*)d_in[3],  (const float*)d_in[7],
                          (const float*)d_in[13], (const float*)d_in[17]);
    prep_b<<<4, 512>>>((const float*)d_in[2],  (const float*)d_in[6],
                       (const float*)d_in[12], (const float*)d_in[16],
                       (const float*)d_in[4],  (const float*)d_in[5],
                       (const float*)d_in[8],  (const float*)d_in[9],
                       (const float*)d_in[14], (const float*)d_in[15],
                       (const float*)d_in[18], (const float*)d_in[19]);

    dim3 grid(BATCH / RR, 2);
    encoder_kernel<<<grid, NTHR>>>(pos, speed,
                                   (const float*)d_in[10], (const float*)d_in[11]);
    decoder_kernel<<<grid, NTHR>>>(pos, speed,
                                   (const float*)d_in[20], (const float*)d_in[21],
                                   (float*)d_out);
}

// round 4
// speedup vs baseline: 1.0002x; 1.0002x over previous
#include <cuda_runtime.h>

#define H     128
#define DD    2
#define TOBS  20
#define PREDN 30
#define BATCH 16384
#define RR    16          // batch rows per block
#define PP    8           // row pairs (RR/2)
#define NTHR  128
#define KT    4
#define NT    (H/KT)      // 32

typedef unsigned long long ull;

// __device__ scratch (allocation-free rule)
__device__ float g_wt[4][H][4*H];       // [w][k][4*j+g], w: 0=pe,1=se,2=sd,3=pd
__device__ float g_b [4][4*H];          // combined bih+bhh, interleaved [4*j+g]
__device__ float g_wi[4][4*H][DD];      // Wih interleaved
__device__ float g_hln[2][BATCH][H];    // layernormed encoder h (0=pos,1=speed)
__device__ float g_cln[2][BATCH][H];    // layernormed encoder c

// ---------- helpers ----------
__device__ __forceinline__ ull pk(float a, float b){
    ull r; asm("mov.b64 %0, {%1, %2};" : "=l"(r) : "f"(a), "f"(b)); return r;
}
__device__ __forceinline__ float2 up(ull v){
    float2 r; asm("mov.b64 {%0, %1}, %2;" : "=f"(r.x), "=f"(r.y) : "l"(v)); return r;
}
__device__ __forceinline__ void fma2(ull& d, ull a, ull b){
    asm("fma.rn.f32x2 %0, %1, %2, %0;" : "+l"(d) : "l"(a), "l"(b));
}
__device__ __forceinline__ float sigm(float x){ return 1.0f/(1.0f + __expf(-x)); }
__device__ __forceinline__ float tanh_(float x){
    float a = fabsf(x);
    float t = 1.0f - 2.0f/(__expf(2.0f*a) + 1.0f);
    return copysignf(t, x);
}

// one K-tile of the 512x128 gate GEMM: 4 k's, 32 FFMA2 per k
#define GTILE(WB, KB) \
    _Pragma("unroll") \
    for (int i_ = 0; i_ < KT; i_++){ \
        const ulonglong2* hp2_ = (const ulonglong2*)(hb + ((KB)+i_)*RR); \
        ulonglong2 q0_=hp2_[0], q1_=hp2_[1], q2_=hp2_[2], q3_=hp2_[3]; \
        ull hp_[PP] = {q0_.x,q0_.y,q1_.x,q1_.y,q2_.x,q2_.y,q3_.x,q3_.y}; \
        float4 wv_ = WB[i_]; \
        ull wg_[4] = {pk(wv_.x,wv_.x), pk(wv_.y,wv_.y), pk(wv_.z,wv_.z), pk(wv_.w,wv_.w)}; \
        _Pragma("unroll") \
        for (int g_ = 0; g_ < 4; g_++){ \
            _Pragma("unroll") \
            for (int p_ = 0; p_ < PP; p_++) fma2(acc[g_][p_], wg_[g_], hp_[p_]); \
        } \
    }

// gates(acc) += Whh @ h  for this thread's unit j. wtj points at unit j's float4 column.
__device__ __forceinline__ void gemm_hh(const float4* __restrict__ wtj,
                                        const float* __restrict__ hb,
                                        ull (&acc)[4][PP]){
    float4 wb0[KT], wb1[KT];
    #pragma unroll
    for (int i = 0; i < KT; i++) wb0[i] = __ldg(wtj + i*H);
    #pragma unroll 1
    for (int kt = 0; kt < NT; kt += 2){
        #pragma unroll
        for (int i = 0; i < KT; i++) wb1[i] = __ldg(wtj + ((kt+1)*KT + i)*H);
        GTILE(wb0, kt*KT)
        if (kt + 2 < NT){
            #pragma unroll
            for (int i = 0; i < KT; i++) wb0[i] = __ldg(wtj + ((kt+2)*KT + i)*H);
        }
        GTILE(wb1, (kt+1)*KT)
    }
}

// acc init: bias + Wih @ x  (x per row from two float2's)
#define ACC_INIT(XA, XB) \
    _Pragma("unroll") \
    for (int g_ = 0; g_ < 4; g_++){ \
        float a0_ = fmaf(wi1[g_], (XA).y, fmaf(wi0[g_], (XA).x, bb[g_])); \
        float a1_ = fmaf(wi1[g_], (XB).y, fmaf(wi0[g_], (XB).x, bb[g_])); \
        acc[g_][p] = pk(a0_, a1_); \
    }

// LSTM activation epilogue: updates cst, produces packed hnew
#define LSTM_ACT() \
    _Pragma("unroll") \
    for (int p_ = 0; p_ < PP; p_++){ \
        float2 iv = up(acc[0][p_]), fv = up(acc[1][p_]); \
        float2 gv = up(acc[2][p_]), ov = up(acc[3][p_]); \
        float2 cv = up(cst[p_]); \
        float c0 = sigm(fv.x)*cv.x + sigm(iv.x)*tanh_(gv.x); \
        float c1 = sigm(fv.y)*cv.y + sigm(iv.y)*tanh_(gv.y); \
        cst[p_] = pk(c0, c1); \
        hnew[p_] = pk(sigm(ov.x)*tanh_(c0), sigm(ov.y)*tanh_(c1)); \
    }

// ---------- prep kernels ----------
__global__ void prep_w(const float* w0, const float* w1, const float* w2, const float* w3){
    const float* W[4] = {w0, w1, w2, w3};
    int idx = blockIdx.x*blockDim.x + threadIdx.x;   // < 4*65536
    int w   = idx >> 16;
    int rem = idx & 65535;
    int k  = rem >> 9;          // 0..127
    int jg = rem & 511;
    int j  = jg >> 2, g = jg & 3;
    g_wt[w][k][jg] = W[w][(g*H + j)*H + k];
}

__global__ void prep_b(const float* wiA, const float* wiB, const float* wiC, const float* wiD,
                       const float* biA, const float* bhA, const float* biB, const float* bhB,
                       const float* biC, const float* bhC, const float* biD, const float* bhD){
    const float* WI[4] = {wiA, wiB, wiC, wiD};
    const float* BI[4] = {biA, biB, biC, biD};
    const float* BH[4] = {bhA, bhB, bhC, bhD};
    int w = blockIdx.x, jg = threadIdx.x;
    int j = jg >> 2, g = jg & 3;
    int row = g*H + j;
    g_b [w][jg]    = BI[w][row] + BH[w][row];
    g_wi[w][jg][0] = WI[w][row*DD + 0];
    g_wi[w][jg][1] = WI[w][row*DD + 1];
}

// ---------- encoder: 20 LSTM steps + fused LayerNorm ----------
__global__ void __launch_bounds__(NTHR)
encoder_kernel(const float* __restrict__ pos, const float* __restrict__ speed,
               const float* __restrict__ ln_g, const float* __restrict__ ln_b){
    int w    = blockIdx.y;               // 0 = pos(pe), 1 = speed(se)
    int base = blockIdx.x * RR;
    int j    = threadIdx.x;
    const float* x = (w == 0) ? pos : speed;

    __shared__ __align__(16) float hbuf[2][H][RR];
    __shared__ float m_s[RR], rs_s[RR];

    float wi0[4], wi1[4], bb[4];
    #pragma unroll
    for (int g = 0; g < 4; g++){
        wi0[g] = g_wi[w][4*j+g][0];
        wi1[g] = g_wi[w][4*j+g][1];
        bb[g]  = g_b [w][4*j+g];
    }
    const float4* wtj = ((const float4*)g_wt[w]) + j;

    ull cst[PP];
    #pragma unroll
    for (int p = 0; p < PP; p++) cst[p] = 0ull;
    #pragma unroll
    for (int p = 0; p < PP; p++) ((ull*)&hbuf[0][j][0])[p] = 0ull;
    __syncthreads();

    for (int t = 0; t < TOBS; t++){
        const float* hb = &hbuf[t & 1][0][0];
        float*       hw = &hbuf[(t + 1) & 1][0][0];
        ull acc[4][PP];
        const float2* xrow = (const float2*)(x + (size_t)t*BATCH*DD + (size_t)base*DD);
        #pragma unroll
        for (int p = 0; p < PP; p++){
            float2 xa = __ldg(&xrow[2*p]), xb = __ldg(&xrow[2*p+1]);
            ACC_INIT(xa, xb)
        }
        gemm_hh(wtj, hb, acc);
        ull hnew[PP];
        LSTM_ACT()
        #pragma unroll
        for (int p = 0; p < PP; p++) ((ull*)&hw[j*RR])[p] = hnew[p];
        __syncthreads();
    }

    // LayerNorm h (final h is in hbuf[TOBS & 1] == hbuf[0])
    float* hf = &hbuf[TOBS & 1][0][0];
    if (j < RR){
        float s1 = 0.f, s2 = 0.f;
        for (int k = 0; k < H; k++){ float v = hf[k*RR + j]; s1 += v; s2 += v*v; }
        float m  = s1 * (1.0f/H);
        float vr = s2 * (1.0f/H) - m*m;
        m_s[j] = m; rs_s[j] = rsqrtf(vr + 1e-5f);
    }
    __syncthreads();
    float lg = ln_g[j], lb = ln_b[j];
    #pragma unroll
    for (int r = 0; r < RR; r++){
        float v = hf[j*RR + r];
        g_hln[w][base + r][j] = (v - m_s[r]) * rs_s[r] * lg + lb;
    }
    // LayerNorm c (stage through the other buffer)
    float* cf = &hbuf[(TOBS & 1) ^ 1][0][0];
    #pragma unroll
    for (int p = 0; p < PP; p++) ((ull*)&cf[j*RR])[p] = cst[p];
    __syncthreads();
    if (j < RR){
        float s1 = 0.f, s2 = 0.f;
        for (int k = 0; k < H; k++){ float v = cf[k*RR + j]; s1 += v; s2 += v*v; }
        float m  = s1 * (1.0f/H);
        float vr = s2 * (1.0f/H) - m*m;
        m_s[j] = m; rs_s[j] = rsqrtf(vr + 1e-5f);
    }
    __syncthreads();
    #pragma unroll
    for (int r = 0; r < RR; r++){
        float v = cf[j*RR + r];
        g_cln[w][base + r][j] = (v - m_s[r]) * rs_s[r] * lg + lb;
    }
}

// ---------- decoder: 30 LSTM steps + FC feedback + output stores ----------
__global__ void __launch_bounds__(NTHR)
decoder_kernel(const float* __restrict__ pos, const float* __restrict__ speed,
               const float* __restrict__ wfc, const float* __restrict__ bfc,
               float* __restrict__ out){
    int chain = blockIdx.y;              // 0: speed chain (sd), 1: pos chain (pd)
    int w     = 2 + chain;
    int base  = blockIdx.x * RR;
    int j     = threadIdx.x;

    __shared__ __align__(16) float hbuf[2][H][RR];
    __shared__ float x_s[RR][2];
    __shared__ float wfc_s[2][H];

    float wi0[4], wi1[4], bb[4];
    #pragma unroll
    for (int g = 0; g < 4; g++){
        wi0[g] = g_wi[w][4*j+g][0];
        wi1[g] = g_wi[w][4*j+g][1];
        bb[g]  = g_b [w][4*j+g];
    }
    const float4* wtj = ((const float4*)g_wt[w]) + j;

    // initial states
    ull cst[PP];
    if (chain == 0){
        #pragma unroll
        for (int r = 0; r < RR; r++)
            hbuf[0][j][r] = g_hln[0][base + r][j] + g_hln[1][base + r][j];
        #pragma unroll
        for (int p = 0; p < PP; p++){
            float c0 = g_cln[0][base + 2*p    ][j] + g_cln[1][base + 2*p    ][j];
            float c1 = g_cln[0][base + 2*p + 1][j] + g_cln[1][base + 2*p + 1][j];
            cst[p] = pk(c0, c1);
        }
    } else {
        #pragma unroll
        for (int r = 0; r < RR; r++)
            hbuf[0][j][r] = g_hln[0][base + r][j];
        #pragma unroll
        for (int p = 0; p < PP; p++)
            cst[p] = pk(g_cln[0][base + 2*p][j], g_cln[0][base + 2*p + 1][j]);
    }
    wfc_s[0][j] = wfc[j];
    wfc_s[1][j] = wfc[H + j];
    float bf0 = bfc[0], bf1 = bfc[1];
    if (j < RR){
        const float* xs = ((chain == 0) ? speed : pos)
                        + (size_t)(TOBS - 1)*BATCH*DD + (size_t)(base + j)*DD;
        x_s[j][0] = xs[0]; x_s[j][1] = xs[1];
    }
    float* outb = out + ((chain == 0) ? (size_t)PREDN*BATCH*DD : (size_t)0);
    __syncthreads();

    for (int t = 0; t < PREDN; t++){
        const float* hb = &hbuf[t & 1][0][0];
        float*       hw = &hbuf[(t + 1) & 1][0][0];
        ull acc[4][PP];
        #pragma unroll
        for (int p = 0; p < PP; p++){
            float2 xa = make_float2(x_s[2*p  ][0], x_s[2*p  ][1]);
            float2 xb = make_float2(x_s[2*p+1][0], x_s[2*p+1][1]);
            ACC_INIT(xa, xb)
        }
        gemm_hh(wtj, hb, acc);
        ull hnew[PP];
        LSTM_ACT()
        #pragma unroll
        for (int p = 0; p < PP; p++) ((ull*)&hw[j*RR])[p] = hnew[p];
        __syncthreads();

        // FC feedback: x_next = h @ Wfc.T + bfc ; also store output
        if (j < 64){
            int r = j >> 2, q = j & 3;
            float s0 = 0.f, s1 = 0.f;
            #pragma unroll
            for (int i = 0; i < 32; i++){
                int jj = q + 4*i;
                float hv = hw[jj*RR + r];
                s0 = fmaf(hv, wfc_s[0][jj], s0);
                s1 = fmaf(hv, wfc_s[1][jj], s1);
            }
            s0 += __shfl_xor_sync(0xffffffffu, s0, 1);
            s0 += __shfl_xor_sync(0xffffffffu, s0, 2);
            s1 += __shfl_xor_sync(0xffffffffu, s1, 1);
            s1 += __shfl_xor_sync(0xffffffffu, s1, 2);
            if (q == 0){
                float o0 = s0 + bf0, o1 = s1 + bf1;
                x_s[r][0] = o0; x_s[r][1] = o1;
                float* op = outb + ((size_t)t*BATCH + base + r)*DD;
                ((float2*)op)[0] = make_float2(o0, o1);
            }
        }
        __syncthreads();
    }
}

// ---------- launch ----------
extern "C" void kernel_launch(void* const* d_in, const int* in_sizes, int n_in,
                              void* d_out, int out_size){
    (void)in_sizes; (void)n_in; (void)out_size;
    const float* pos   = (const float*)d_in[0];
    const float* speed = (const float*)d_in[1];

    prep_w<<<1024, 256>>>((const float*)d_in[3],  (const float*)d_in[7],
                          (const float*)d_in[13], (const float*)d_in[17]);
    prep_b<<<4, 512>>>((const float*)d_in[2],  (const float*)d_in[6],
                       (const float*)d_in[12], (const float*)d_in[16],
                       (const float*)d_in[4],  (const float*)d_in[5],
                       (const float*)d_in[8],  (const float*)d_in[9],
                       (const float*)d_in[14], (const float*)d_in[15],
                       (const float*)d_in[18], (const float*)d_in[19]);

    dim3 grid(BATCH / RR, 2);
    encoder_kernel<<<grid, NTHR>>>(pos, speed,
                                   (const float*)d_in[10], (const float*)d_in[11]);
    decoder_kernel<<<grid, NTHR>>>(pos, speed,
                                   (const float*)d_in[20], (const float*)d_in[21],
                                   (float*)d_out);
}

// round 16
// speedup vs baseline: 1.5554x; 1.5551x over previous
#include <cuda_runtime.h>
#include <cuda_fp16.h>
#include <cstdint>

#define H     128
#define TOBS  20
#define PREDN 30
#define BATCH 16384
#define RR    32
#define NTHR  512

// smem layout (bytes)
#define SM_AW    0                       // Whi fragments: 131072
#define SM_STAGE 131072                  // fp32 gates [512][34]: 69632
#define SM_BH    (SM_STAGE + 69632)      // h hi B-frags: 8192
#define SM_BL    (SM_BH + 8192)          // h lo B-frags: 8192
#define SM_FOLD  (SM_BL + 8192)          // float4[512]: 8192
#define SM_RED   (SM_FOLD + 8192)        // float2[16][32]: 4096
#define SM_XS    (SM_RED + 4096)         // float2[32]: 256
#define SM_WFC   (SM_XS + 256)           // float2[128]: 1024
#define SM_LNP   (SM_WFC + 1024)         // float2[128]: 1024
#define SM_SZ    (SM_LNP + 1024)         // 231680 <= 232448

typedef unsigned short ushort;

// device scratch
__device__ ushort g_wA[4][2][32][8][32][8]; // [lstm][hi/lo][mt][kt][lane][reg*2+half]
__device__ float4 g_fold[4][512];           // (wi0, wi1, bih+bhh, 0) per gate slot 4j+g
__device__ float  g_hln[2][BATCH][H];
__device__ float  g_cln[2][BATCH][H];

__device__ __forceinline__ float sigm(float x){ return 1.0f/(1.0f + __expf(-x)); }
__device__ __forceinline__ float tanh_(float x){
    float a = fabsf(x);
    float t = 1.0f - 2.0f/(__expf(2.0f*a) + 1.0f);
    return copysignf(t, x);
}

__device__ __forceinline__ void mma16816(float* c, const uint32_t* a, const uint32_t* b){
    asm volatile("mma.sync.aligned.m16n8k16.row.col.f32.f16.f16.f32 "
        "{%0,%1,%2,%3}, {%4,%5,%6,%7}, {%8,%9}, {%0,%1,%2,%3};"
        : "+f"(c[0]), "+f"(c[1]), "+f"(c[2]), "+f"(c[3])
        : "r"(a[0]), "r"(a[1]), "r"(a[2]), "r"(a[3]), "r"(b[0]), "r"(b[1]));
}

// ---------------- prep ----------------
__global__ void prep_wA(const float* w0, const float* w1, const float* w2, const float* w3){
    const float* W[4] = {w0, w1, w2, w3};
    int idx = blockIdx.x*blockDim.x + threadIdx.x;   // 4*65536
    int l = idx >> 16, rem = idx & 65535;
    int m = rem >> 7, k = rem & 127;                 // m = gate idx 4j+g
    int j = m >> 2, g = m & 3;
    float v = W[l][(g*H + j)*H + k];
    __half hi = __float2half_rn(v);
    __half lo = __float2half_rn(v - __half2float(hi));
    int mt = m >> 4, kt = k >> 4;
    int ml = m & 15, kl = k & 15;
    int lane = (ml & 7)*4 + ((kl & 7) >> 1);
    int reg  = (kl >> 3)*2 + (ml >> 3);
    int hf   = k & 1;
    g_wA[l][0][mt][kt][lane][reg*2 + hf] = __half_as_ushort(hi);
    g_wA[l][1][mt][kt][lane][reg*2 + hf] = __half_as_ushort(lo);
}

__global__ void prep_fold(const float* wiA, const float* biA, const float* bhA,
                          const float* wiB, const float* biB, const float* bhB,
                          const float* wiC, const float* biC, const float* bhC,
                          const float* wiD, const float* biD, const float* bhD){
    const float* WI[4] = {wiA, wiB, wiC, wiD};
    const float* BI[4] = {biA, biB, biC, biD};
    const float* BH[4] = {bhA, bhB, bhC, bhD};
    int w = blockIdx.x, t = threadIdx.x;
    int u = t >> 2, g = t & 3;
    int row = g*H + u;
    g_fold[w][u*4 + g] = make_float4(WI[w][row*2], WI[w][row*2 + 1], BI[w][row] + BH[w][row], 0.f);
}

// ---------------- shared pieces ----------------
// GEMM + STS of acc into stage. warp: wm = w>>1 (gate block of 64), wn = w&1 (16 rows)
__device__ __forceinline__ void gemm_step(char* sm, const uint4* __restrict__ gwlo,
                                          int wm, int wn, int lane){
    float acc[4][2][4];
    #pragma unroll
    for (int i = 0; i < 4; i++)
        #pragma unroll
        for (int n = 0; n < 2; n++)
            #pragma unroll
            for (int q = 0; q < 4; q++) acc[i][n][q] = 0.f;

    const uint4*    aw = (const uint4*)(sm + SM_AW);
    const uint32_t* bh = (const uint32_t*)(sm + SM_BH);
    const uint32_t* bl = (const uint32_t*)(sm + SM_BL);

    uint4 loA[2][4];
    #pragma unroll
    for (int i = 0; i < 4; i++){
        loA[0][i] = __ldg(gwlo + ((wm*4 + i)*8 + 0)*32 + lane);
        loA[1][i] = __ldg(gwlo + ((wm*4 + i)*8 + 1)*32 + lane);
    }

    #pragma unroll
    for (int kt = 0; kt < 8; kt++){
        uint32_t bhh[2][2], bhl[2][2];
        #pragma unroll
        for (int n = 0; n < 2; n++){
            int nt = wn*2 + n;
            bhh[n][0] = bh[((kt*4 + nt)*2 + 0)*32 + lane];
            bhh[n][1] = bh[((kt*4 + nt)*2 + 1)*32 + lane];
            bhl[n][0] = bl[((kt*4 + nt)*2 + 0)*32 + lane];
            bhl[n][1] = bl[((kt*4 + nt)*2 + 1)*32 + lane];
        }
        uint4 ahi[4];
        #pragma unroll
        for (int i = 0; i < 4; i++) ahi[i] = aw[((wm*4 + i)*8 + kt)*32 + lane];
        #pragma unroll
        for (int i = 0; i < 4; i++)
            #pragma unroll
            for (int n = 0; n < 2; n++){
                mma16816(acc[i][n], (const uint32_t*)&ahi[i], bhh[n]);
                mma16816(acc[i][n], (const uint32_t*)&ahi[i], bhl[n]);
            }
        uint4* cur = loA[kt & 1];
        #pragma unroll
        for (int i = 0; i < 4; i++)
            #pragma unroll
            for (int n = 0; n < 2; n++)
                mma16816(acc[i][n], (const uint32_t*)&cur[i], bhh[n]);
        if (kt + 2 < 8){
            #pragma unroll
            for (int i = 0; i < 4; i++)
                cur[i] = __ldg(gwlo + ((wm*4 + i)*8 + kt + 2)*32 + lane);
        }
    }

    float* st = (float*)(sm + SM_STAGE);
    int mr = (lane >> 2), cc = 2*(lane & 3);
    #pragma unroll
    for (int i = 0; i < 4; i++)
        #pragma unroll
        for (int n = 0; n < 2; n++){
            int mrow = wm*64 + i*16 + mr;
            int col  = wn*16 + n*8 + cc;
            *(float2*)&st[(mrow    )*34 + col] = make_float2(acc[i][n][0], acc[i][n][1]);
            *(float2*)&st[(mrow + 8)*34 + col] = make_float2(acc[i][n][2], acc[i][n][3]);
        }
}

// write h into B-fragment arrays as fp16 hi/lo
__device__ __forceinline__ void write_hfrag(char* sm, int j, int r, float h){
    int kt = j >> 4, reg = (j >> 3) & 1, hf = j & 1;
    int lane = (r & 7)*4 + ((j & 7) >> 1);
    int nt = r >> 3;
    int hw = (((kt*4 + nt)*2 + reg)*32 + lane)*2 + hf;
    __half hh = __float2half_rn(h);
    ((ushort*)(sm + SM_BH))[hw] = __half_as_ushort(hh);
    ((ushort*)(sm + SM_BL))[hw] = __half_as_ushort(__float2half_rn(h - __half2float(hh)));
}

// ---------------- encoder ----------------
__global__ void __launch_bounds__(NTHR, 1)
encoder_kernel(const float* __restrict__ pos, const float* __restrict__ speed,
               const float* __restrict__ ln_g, const float* __restrict__ ln_b){
    extern __shared__ char sm[];
    int tid = threadIdx.x, lane = tid & 31;
    int wm = (tid >> 5) >> 1, wn = (tid >> 5) & 1;
    int l = blockIdx.y, base = blockIdx.x*RR;
    int r = tid & 31, grp = tid >> 5, j0 = grp*8;
    const float* x = (l == 0) ? pos : speed;

    { // init smem
        const uint4* src = (const uint4*)g_wA[l][0];
        uint4* dst = (uint4*)(sm + SM_AW);
        for (int i = tid; i < 8192; i += NTHR) dst[i] = src[i];
        const float4* fs = (const float4*)g_fold[l];
        float4* fd = (float4*)(sm + SM_FOLD);
        if (tid < 512) fd[tid] = fs[tid];
        uint32_t* bz = (uint32_t*)(sm + SM_BH);
        for (int i = tid; i < 4096; i += NTHR) bz[i] = 0;   // zero BH+BL
        if (tid < 128) ((float2*)(sm + SM_LNP))[tid] = make_float2(__ldg(&ln_g[tid]), __ldg(&ln_b[tid]));
    }
    float cc[8];
    #pragma unroll
    for (int u = 0; u < 8; u++) cc[u] = 0.f;
    __syncthreads();

    const uint4* gwlo = (const uint4*)g_wA[l][1];
    float* st = (float*)(sm + SM_STAGE);
    const float4* fold = (const float4*)(sm + SM_FOLD);

    for (int t = 0; t < TOBS; t++){
        gemm_step(sm, gwlo, wm, wn, lane);
        __syncthreads();
        float2 xv = __ldg((const float2*)(x + ((size_t)t*BATCH + base + r)*2));
        int last = (t == TOBS - 1);
        #pragma unroll
        for (int u = 0; u < 8; u++){
            int j = j0 + u;
            float4 fi = fold[j*4+0], ff = fold[j*4+1], fg = fold[j*4+2], fo = fold[j*4+3];
            float gi = st[(4*j+0)*34 + r] + fmaf(fi.x, xv.x, fmaf(fi.y, xv.y, fi.z));
            float gf = st[(4*j+1)*34 + r] + fmaf(ff.x, xv.x, fmaf(ff.y, xv.y, ff.z));
            float gg = st[(4*j+2)*34 + r] + fmaf(fg.x, xv.x, fmaf(fg.y, xv.y, fg.z));
            float go = st[(4*j+3)*34 + r] + fmaf(fo.x, xv.x, fmaf(fo.y, xv.y, fo.z));
            float c = sigm(gf)*cc[u] + sigm(gi)*tanh_(gg);
            cc[u] = c;
            float h = sigm(go)*tanh_(c);
            if (!last) write_hfrag(sm, j, r, h);
            else { st[(4*j+0)*34 + r] = h; st[(4*j+1)*34 + r] = c; }
        }
        __syncthreads();
    }

    // LayerNorm (h in rows 4j+0, c in rows 4j+1)
    float2* red = (float2*)(sm + SM_RED);
    if (tid < 64){
        int rr = tid & 31, which = tid >> 5;
        float s1 = 0.f, s2 = 0.f;
        for (int j = 0; j < H; j++){
            float v = st[(4*j + which)*34 + rr];
            s1 += v; s2 += v*v;
        }
        float m  = s1*(1.f/H);
        float rs = rsqrtf(s2*(1.f/H) - m*m + 1e-5f);
        red[which*32 + rr] = make_float2(m, rs);
    }
    __syncthreads();
    {
        float2 mh = red[r], mc = red[32 + r];
        const float2* lnp = (const float2*)(sm + SM_LNP);
        int grow = base + r;
        #pragma unroll
        for (int u = 0; u < 8; u++){
            int j = j0 + u;
            float2 p = lnp[j];
            g_hln[l][grow][j] = (st[(4*j+0)*34 + r] - mh.x)*mh.y*p.x + p.y;
            g_cln[l][grow][j] = (st[(4*j+1)*34 + r] - mc.x)*mc.y*p.x + p.y;
        }
    }
}

// ---------------- decoder ----------------
__global__ void __launch_bounds__(NTHR, 1)
decoder_kernel(const float* __restrict__ pos, const float* __restrict__ speed,
               const float* __restrict__ wfc, const float* __restrict__ bfc,
               float* __restrict__ out){
    extern __shared__ char sm[];
    int tid = threadIdx.x, lane = tid & 31;
    int wm = (tid >> 5) >> 1, wn = (tid >> 5) & 1;
    int chain = blockIdx.y, l = 2 + chain, base = blockIdx.x*RR;
    int r = tid & 31, grp = tid >> 5, j0 = grp*8;

    { // init smem
        const uint4* src = (const uint4*)g_wA[l][0];
        uint4* dst = (uint4*)(sm + SM_AW);
        for (int i = tid; i < 8192; i += NTHR) dst[i] = src[i];
        const float4* fs = (const float4*)g_fold[l];
        float4* fd = (float4*)(sm + SM_FOLD);
        if (tid < 512) fd[tid] = fs[tid];
        if (tid < 128) ((float2*)(sm + SM_WFC))[tid] = make_float2(__ldg(&wfc[tid]), __ldg(&wfc[H + tid]));
        if (tid < 32){
            const float* xs = ((chain == 0) ? speed : pos)
                            + ((size_t)(TOBS - 1)*BATCH + base + tid)*2;
            ((float2*)(sm + SM_XS))[tid] = make_float2(xs[0], xs[1]);
        }
    }
    // initial state
    float cc[8];
    {
        int grow = base + r;
        #pragma unroll
        for (int u = 0; u < 8; u++){
            int j = j0 + u;
            float h0, c0;
            if (chain == 0){
                h0 = g_hln[0][grow][j] + g_hln[1][grow][j];
                c0 = g_cln[0][grow][j] + g_cln[1][grow][j];
            } else {
                h0 = g_hln[0][grow][j];
                c0 = g_cln[0][grow][j];
            }
            cc[u] = c0;
            write_hfrag(sm, j, r, h0);
        }
    }
    __syncthreads();

    const uint4* gwlo = (const uint4*)g_wA[l][1];
    float* st = (float*)(sm + SM_STAGE);
    const float4* fold = (const float4*)(sm + SM_FOLD);
    const float2* wfcs = (const float2*)(sm + SM_WFC);
    float2* red = (float2*)(sm + SM_RED);
    float2* xs  = (float2*)(sm + SM_XS);
    float bf0 = __ldg(&bfc[0]), bf1 = __ldg(&bfc[1]);
    float2* outp = (float2*)out + ((chain == 0) ? (size_t)PREDN*BATCH : 0);

    for (int t = 0; t < PREDN; t++){
        gemm_step(sm, gwlo, wm, wn, lane);
        __syncthreads();
        float2 xv = xs[r];
        float fc0 = 0.f, fc1 = 0.f;
        #pragma unroll
        for (int u = 0; u < 8; u++){
            int j = j0 + u;
            float4 fi = fold[j*4+0], ff = fold[j*4+1], fg = fold[j*4+2], fo = fold[j*4+3];
            float gi = st[(4*j+0)*34 + r] + fmaf(fi.x, xv.x, fmaf(fi.y, xv.y, fi.z));
            float gf = st[(4*j+1)*34 + r] + fmaf(ff.x, xv.x, fmaf(ff.y, xv.y, ff.z));
            float gg = st[(4*j+2)*34 + r] + fmaf(fg.x, xv.x, fmaf(fg.y, xv.y, fg.z));
            float go = st[(4*j+3)*34 + r] + fmaf(fo.x, xv.x, fmaf(fo.y, xv.y, fo.z));
            float c = sigm(gf)*cc[u] + sigm(gi)*tanh_(gg);
            cc[u] = c;
            float h = sigm(go)*tanh_(c);
            float2 wv = wfcs[j];
            fc0 = fmaf(h, wv.x, fc0);
            fc1 = fmaf(h, wv.y, fc1);
            write_hfrag(sm, j, r, h);
        }
        red[grp*32 + r] = make_float2(fc0, fc1);
        __syncthreads();
        if (tid < 32){
            float s0 = bf0, s1 = bf1;
            #pragma unroll
            for (int g = 0; g < 16; g++){
                float2 p = red[g*32 + tid];
                s0 += p.x; s1 += p.y;
            }
            float2 xo = make_float2(s0, s1);
            xs[tid] = xo;
            outp[(size_t)t*BATCH + base + tid] = xo;
        }
    }
}

// ---------------- launch ----------------
extern "C" void kernel_launch(void* const* d_in, const int* in_sizes, int n_in,
                              void* d_out, int out_size){
    (void)in_sizes; (void)n_in; (void)out_size;
    cudaFuncSetAttribute(encoder_kernel, cudaFuncAttributeMaxDynamicSharedMemorySize, SM_SZ);
    cudaFuncSetAttribute(decoder_kernel, cudaFuncAttributeMaxDynamicSharedMemorySize, SM_SZ);

    prep_wA<<<512, 512>>>((const float*)d_in[3],  (const float*)d_in[7],
                          (const float*)d_in[13], (const float*)d_in[17]);
    prep_fold<<<4, 512>>>((const float*)d_in[2],  (const float*)d_in[4],  (const float*)d_in[5],
                          (const float*)d_in[6],  (const float*)d_in[8],  (const float*)d_in[9],
                          (const float*)d_in[12], (const float*)d_in[14], (const float*)d_in[15],
                          (const float*)d_in[16], (const float*)d_in[18], (const float*)d_in[19]);

    dim3 grid(BATCH / RR, 2);
    encoder_kernel<<<grid, NTHR, SM_SZ>>>((const float*)d_in[0], (const float*)d_in[1],
                                          (const float*)d_in[10], (const float*)d_in[11]);
    decoder_kernel<<<grid, NTHR, SM_SZ>>>((const float*)d_in[0], (const float*)d_in[1],
                                          (const float*)d_in[20], (const float*)d_in[21],
                                          (float*)d_out);
}